// round 14
// baseline (speedup 1.0000x reference)
#include <cuda_runtime.h>
#include <math.h>
#include <stdint.h>

#define NPTS 8192
#define MB   64
#define NBALL 128
#define DIM  64
#define NH   8
#define EHD  8
#define HID  256
#define EPSF 1.1920929e-07f

// ---------------- scratch ----------------
__device__ float    g_xat[NH * NPTS * EHD];
__device__ float    g_keyst[NH * NBALL * EHD];
__device__ int      g_idx[NH * NPTS * 2];
__device__ float    g_h[NPTS * DIM];       // residual stream
// packed tf32 B-fragments, 4 words/lane = [k8even r0, k8even r1, k8odd r0, k8odd r1]
__device__ uint32_t g_w1p[16384];   // [n8:32][k8p:4][lane:32][word:4]
__device__ uint32_t g_w2p[16384];
__device__ uint32_t g_w3p[16384];   // [n8:8][k8p:16][lane:32][word:4]

__device__ __forceinline__ uint32_t f2tf32(float f) {
    uint32_t u;
    asm("cvt.rna.tf32.f32 %0, %1;" : "=r"(u) : "f"(f));
    return u;
}
__device__ __forceinline__ void mma_tf32(float* c, const uint32_t* a,
                                         uint32_t b0, uint32_t b1) {
    asm volatile(
        "mma.sync.aligned.m16n8k8.row.col.f32.tf32.tf32.f32 "
        "{%0,%1,%2,%3}, {%4,%5,%6,%7}, {%8,%9}, {%0,%1,%2,%3};"
        : "+f"(c[0]), "+f"(c[1]), "+f"(c[2]), "+f"(c[3])
        : "r"(a[0]), "r"(a[1]), "r"(a[2]), "r"(a[3]), "r"(b0), "r"(b1));
}

// ---------------- K1: ball prep (tree reductions) + weight frag build -------
__global__ void k_prep(const float* __restrict__ x,
                       const float* __restrict__ pos,
                       const float* __restrict__ n1w,
                       const float* __restrict__ w1,
                       const float* __restrict__ w2,
                       const float* __restrict__ w3) {
    int blk = blockIdx.x, tid = threadIdx.x;
    if (blk >= NBALL) {
        int grp = blk - NBALL;
        int i = (grp & 63) * 256 + tid;       // 0..16383
        int word = i & 3, lane = (i >> 2) & 31;
        int j = word >> 1, r = word & 1;
        if (grp < 64) {
            int k8p = (i >> 7) & 3, n8 = i >> 9;
            int k8 = k8p * 2 + j;
            int k = k8 * 8 + (lane & 3) + r * 4;
            int n = n8 * 8 + (lane >> 2);
            g_w1p[i] = f2tf32(w1[n * DIM + k]);
            g_w2p[i] = f2tf32(w2[n * DIM + k]);
        } else {
            int k8p = (i >> 7) & 15, n8 = i >> 11;
            int k8 = k8p * 2 + j;
            int k = k8 * 8 + (lane & 3) + r * 4;
            int n = n8 * 8 + (lane >> 2);
            g_w3p[i] = f2tf32(w3[n * HID + k]);
        }
        return;
    }
    __shared__ float ps[MB][DIM + 1];
    __shared__ float pp[4][DIM];
    __shared__ float pm[DIM];
    __shared__ float wsm[DIM];
    const float* xb = x + blk * (MB * DIM);
    const float* pb = pos + blk * (MB * DIM);
    for (int i = tid; i < MB * DIM; i += 256) ps[i >> 6][i & 63] = pb[i];
    if (tid < DIM) wsm[tid] = n1w[tid];
    int r = tid >> 2, part = tid & 3, d0 = part * 16;
    float xv[16];
    {
        const float4* xr4 = (const float4*)(xb + r * DIM + d0);
        float4 a0 = xr4[0], a1 = xr4[1], a2 = xr4[2], a3 = xr4[3];
        xv[0] = a0.x; xv[1] = a0.y; xv[2] = a0.z; xv[3] = a0.w;
        xv[4] = a1.x; xv[5] = a1.y; xv[6] = a1.z; xv[7] = a1.w;
        xv[8] = a2.x; xv[9] = a2.y; xv[10] = a2.z; xv[11] = a2.w;
        xv[12] = a3.x; xv[13] = a3.y; xv[14] = a3.z; xv[15] = a3.w;
    }
    float ss = 0.f;
    #pragma unroll
    for (int j = 0; j < 16; j++) ss += xv[j] * xv[j];
    ss += __shfl_xor_sync(0xffffffffu, ss, 1);
    ss += __shfl_xor_sync(0xffffffffu, ss, 2);
    float rs = rsqrtf(ss * (1.f / DIM) + EPSF);
    __syncthreads();
    {
        int d = tid & 63, c = tid >> 6;
        float s = 0.f;
        #pragma unroll
        for (int rr = 0; rr < 16; rr++) s += ps[c * 16 + rr][d];
        pp[c][d] = s;
    }
    __syncthreads();
    if (tid < DIM)
        pm[tid] = (pp[0][tid] + pp[1][tid] + pp[2][tid] + pp[3][tid]) * (1.f / MB);
    __syncthreads();
    float vals[16];
    #pragma unroll
    for (int j = 0; j < 16; j++) {
        int d = d0 + j;
        vals[j] = xv[j] * rs * wsm[d] + ps[r][d] - pm[d];
        ps[r][d] = vals[j];
    }
    {
        int n = blk * MB + r;
        float* o0 = g_xat + (part * 2) * (NPTS * EHD) + n * EHD;
        float* o1 = o0 + NPTS * EHD;
        ((float4*)o0)[0] = make_float4(vals[0], vals[1], vals[2], vals[3]);
        ((float4*)o0)[1] = make_float4(vals[4], vals[5], vals[6], vals[7]);
        ((float4*)o1)[0] = make_float4(vals[8], vals[9], vals[10], vals[11]);
        ((float4*)o1)[1] = make_float4(vals[12], vals[13], vals[14], vals[15]);
    }
    __syncthreads();
    {
        int d = tid & 63, c = tid >> 6;
        float s = 0.f;
        #pragma unroll
        for (int rr = 0; rr < 16; rr++) s += ps[c * 16 + rr][d];
        pp[c][d] = s;
    }
    __syncthreads();
    if (tid < DIM) {
        float s = (pp[0][tid] + pp[1][tid] + pp[2][tid] + pp[3][tid]) * (1.f / MB);
        g_keyst[(tid >> 3) * (NBALL * EHD) + blk * EHD + (tid & 7)] = s;
    }
}

// ---------------- K2: routing (smem-cached keys, 512 blocks x 128 thr) ------
__global__ void k_route() {
    __shared__ float4 ks[NBALL * 2];
    int h = blockIdx.x >> 6;
    int n = (blockIdx.x & 63) * 128 + threadIdx.x;
    const float4* kg = (const float4*)(g_keyst + h * (NBALL * EHD));
    ks[threadIdx.x] = kg[threadIdx.x];
    ks[threadIdx.x + 128] = kg[threadIdx.x + 128];
    __syncthreads();
    const float4* qp = (const float4*)(g_xat + h * (NPTS * EHD) + n * EHD);
    float4 qa = qp[0], qb = qp[1];
    float v0 = -3.4e38f, v1 = -3.4e38f;
    int i0 = 0, i1 = 0;
    #pragma unroll 4
    for (int b = 0; b < NBALL; b++) {
        float4 kA = ks[b * 2], kB = ks[b * 2 + 1];
        float s = qa.x * kA.x + qa.y * kA.y + qa.z * kA.z + qa.w * kA.w
                + qb.x * kB.x + qb.y * kB.y + qb.z * kB.z + qb.w * kB.w;
        if (s > v0) { v1 = v0; i1 = i0; v0 = s; i0 = b; }
        else if (s > v1) { v1 = s; i1 = b; }
    }
    int o = (h * NPTS + n) * 2;
    g_idx[o] = i0;
    g_idx[o + 1] = i1;
}

// ---------------- K3: attention (one warp per (n,h), coalesced lane-pair) ----
__global__ void k_attn(const float* __restrict__ x) {
    int n = blockIdx.x;
    int h = threadIdx.x >> 5, lane = threadIdx.x & 31;
    const float* hb = g_xat + h * (NPTS * EHD);
    const float4* qp = (const float4*)(hb + n * EHD);
    float4 qa = qp[0], qb = qp[1];
    float4 qh = (lane & 1) ? qb : qa;
    int base = (h * NPTS + n) * 2;
    int b0 = g_idx[base], b1 = g_idx[base + 1];
    const float4* p0 = (const float4*)(hb + b0 * (MB * EHD));
    const float4* p1 = (const float4*)(hb + b1 * (MB * EHD));
    const float scale = 0.35355339059327373f;  // 1/sqrt(8)

    float4 v[8];
    #pragma unroll
    for (int c = 0; c < 4; c++) v[c] = p0[c * 32 + lane];
    #pragma unroll
    for (int c = 0; c < 4; c++) v[4 + c] = p1[c * 32 + lane];

    float s[8];
    #pragma unroll
    for (int i = 0; i < 8; i++) {
        float part = qh.x * v[i].x + qh.y * v[i].y + qh.z * v[i].z + qh.w * v[i].w;
        s[i] = (part + __shfl_xor_sync(0xffffffffu, part, 1)) * scale;
    }
    float m = s[0];
    #pragma unroll
    for (int i = 1; i < 8; i++) m = fmaxf(m, s[i]);
    #pragma unroll
    for (int o = 16; o >= 1; o >>= 1) m = fmaxf(m, __shfl_xor_sync(0xffffffffu, m, o));
    float p[8], lsum = 0.f;
    #pragma unroll
    for (int i = 0; i < 8; i++) { p[i] = __expf(s[i] - m); lsum += p[i]; }
    #pragma unroll
    for (int o = 16; o >= 1; o >>= 1) lsum += __shfl_xor_sync(0xffffffffu, lsum, o);
    float inv = 2.f / lsum;   // every row counted twice across the warp

    float4 acc = make_float4(0.f, 0.f, 0.f, 0.f);
    #pragma unroll
    for (int i = 0; i < 8; i++) {
        acc.x += p[i] * v[i].x; acc.y += p[i] * v[i].y;
        acc.z += p[i] * v[i].z; acc.w += p[i] * v[i].w;
    }
    #pragma unroll
    for (int o = 2; o <= 16; o <<= 1) {
        acc.x += __shfl_xor_sync(0xffffffffu, acc.x, o);
        acc.y += __shfl_xor_sync(0xffffffffu, acc.y, o);
        acc.z += __shfl_xor_sync(0xffffffffu, acc.z, o);
        acc.w += __shfl_xor_sync(0xffffffffu, acc.w, o);
    }
    if (lane < 2) {
        int off = n * DIM + h * EHD + lane * 4;
        float4 xr = *(const float4*)(x + off);
        float4 o;
        o.x = xr.x + acc.x * inv;
        o.y = xr.y + acc.y * inv;
        o.z = xr.z + acc.z * inv;
        o.w = xr.w + acc.w * inv;
        *(float4*)(g_h + off) = o;
    }
}

// ---------------- K4: fused MLP, 16 rows/CTA, 3 CTAs/SM ----------------
// grid 512, 256 threads. Phase 1: warp w -> hidden n8 {4w..4w+3} (ns pairs).
// Phase 2: warp w -> output n8 = w. Hidden handoff via smem tf32 A-frags.
__global__ void __launch_bounds__(256, 3)
k_mlp(const float* __restrict__ n2w,
      const float* __restrict__ b1p,
      const float* __restrict__ b2p,
      const float* __restrict__ b3p,
      float* __restrict__ y) {
    __shared__ uint32_t safr[8 * 32 * 4];       // 4KB  input A-frags (1 m16)
    __shared__ uint32_t hfr[32 * 32 * 4];       // 16KB hidden A-frags (1 m16)
    __shared__ float sb1[HID], sb2[HID];
    int tid = threadIdx.x;
    int r0 = blockIdx.x * 16;
    sb1[tid] = b1p[tid];
    sb2[tid] = b2p[tid];
    // ---- rmsnorm: thread -> row rr (0..15), dims p*4..p*4+3 ----
    {
        int rr = tid >> 4, p = tid & 15;
        float4 hv = *(const float4*)(g_h + (r0 + rr) * DIM + p * 4);
        float ss = hv.x * hv.x + hv.y * hv.y + hv.z * hv.z + hv.w * hv.w;
        ss += __shfl_xor_sync(0xffffffffu, ss, 1);
        ss += __shfl_xor_sync(0xffffffffu, ss, 2);
        ss += __shfl_xor_sync(0xffffffffu, ss, 4);
        ss += __shfl_xor_sync(0xffffffffu, ss, 8);
        float rs = rsqrtf(ss * (1.f / DIM) + EPSF);
        float hvv[4] = {hv.x, hv.y, hv.z, hv.w};
        #pragma unroll
        for (int j = 0; j < 4; j++) {
            int k = p * 4 + j;
            float tv = hvv[j] * rs * n2w[k];
            int lane_t = ((rr & 7) << 2) | (k & 3);
            int reg = ((rr >> 3) & 1) | (((k >> 2) & 1) << 1);
            safr[(((k >> 3) * 32 + lane_t) << 2) + reg] = f2tf32(tv);
        }
    }
    __syncthreads();
    int warp = tid >> 5, lane = tid & 31;
    // ---- phase 1: dual GEMM (1 m16), ns pairs ----
    {
        float c1[4][4], c2[4][4];
        #pragma unroll
        for (int n = 0; n < 4; n++)
            #pragma unroll
            for (int j = 0; j < 4; j++) { c1[n][j] = 0.f; c2[n][j] = 0.f; }
        #pragma unroll
        for (int k8p = 0; k8p < 4; k8p++) {
            #pragma unroll
            for (int nsp = 0; nsp < 2; nsp++) {
                uint4 b1v[2], b2v[2];
                #pragma unroll
                for (int ns2 = 0; ns2 < 2; ns2++) {
                    int n8 = warp * 4 + nsp * 2 + ns2;
                    int bi = (((n8 * 4 + k8p) * 32 + lane) << 2);
                    b1v[ns2] = *(const uint4*)(g_w1p + bi);
                    b2v[ns2] = *(const uint4*)(g_w2p + bi);
                }
                #pragma unroll
                for (int j = 0; j < 2; j++) {
                    int k8 = k8p * 2 + j;
                    uint4 av = *(const uint4*)(safr + ((k8 * 32 + lane) << 2));
                    uint32_t a[4] = {av.x, av.y, av.z, av.w};
                    #pragma unroll
                    for (int ns2 = 0; ns2 < 2; ns2++) {
                        int ns = nsp * 2 + ns2;
                        uint32_t w10 = j ? b1v[ns2].z : b1v[ns2].x;
                        uint32_t w11 = j ? b1v[ns2].w : b1v[ns2].y;
                        uint32_t w20 = j ? b2v[ns2].z : b2v[ns2].x;
                        uint32_t w21 = j ? b2v[ns2].w : b2v[ns2].y;
                        mma_tf32(c1[ns], a, w10, w11);
                        mma_tf32(c2[ns], a, w20, w21);
                    }
                }
            }
        }
        // SwiGLU epilogue -> smem hidden A-fragments
        int ka = 2 * (lane & 3);
        int lta = ((lane >> 2) << 2) | (ka & 3);
        int ltb = ((lane >> 2) << 2) | ((ka + 1) & 3);
        int khi = (ka >> 2) << 1;
        #pragma unroll
        for (int ns = 0; ns < 4; ns++) {
            int k8h = warp * 4 + ns;
            int colb = k8h * 8 + ka;
            float bb1a = sb1[colb], bb1b = sb1[colb + 1];
            float bb2a = sb2[colb], bb2b = sb2[colb + 1];
            uint32_t* basep = hfr + ((k8h * 32) << 2);
            #pragma unroll
            for (int half = 0; half < 2; half++) {
                float u1a = c1[ns][half * 2] + bb1a;
                float u1b = c1[ns][half * 2 + 1] + bb1b;
                float ha = (c2[ns][half * 2] + bb2a) * u1a * (1.f / (1.f + __expf(-u1a)));
                float hb = (c2[ns][half * 2 + 1] + bb2b) * u1b * (1.f / (1.f + __expf(-u1b)));
                basep[(lta << 2) + (half | khi)] = f2tf32(ha);
                basep[(ltb << 2) + (half | khi)] = f2tf32(hb);
            }
        }
    }
    __syncthreads();
    // ---- phase 2: down-proj (1 m16), warp w -> output n8 = w ----
    {
        float c[4] = {0.f, 0.f, 0.f, 0.f};
        #pragma unroll 4
        for (int k8p = 0; k8p < 16; k8p++) {
            uint4 bv = *(const uint4*)(g_w3p + (((warp * 16 + k8p) * 32 + lane) << 2));
            #pragma unroll
            for (int j = 0; j < 2; j++) {
                int k8 = k8p * 2 + j;
                uint32_t w0 = j ? bv.z : bv.x;
                uint32_t w1 = j ? bv.w : bv.y;
                uint4 av = *(const uint4*)(hfr + ((k8 * 32 + lane) << 2));
                uint32_t a[4] = {av.x, av.y, av.z, av.w};
                mma_tf32(c, a, w0, w1);
            }
        }
        int colb = warp * 8 + 2 * (lane & 3);
        float bva = b3p[colb], bvb = b3p[colb + 1];
        #pragma unroll
        for (int half = 0; half < 2; half++) {
            int row = r0 + (lane >> 2) + half * 8;
            float2 hres = *(const float2*)(g_h + row * DIM + colb);
            float2 o;
            o.x = hres.x + c[half * 2] + bva;
            o.y = hres.y + c[half * 2 + 1] + bvb;
            *(float2*)(y + row * DIM + colb) = o;
        }
    }
}

// ---------------- launch ----------------
extern "C" void kernel_launch(void* const* d_in, const int* in_sizes, int n_in,
                              void* d_out, int out_size) {
    const float* x    = (const float*)d_in[0];
    const float* pos  = (const float*)d_in[1];
    const float* n1w  = (const float*)d_in[2];
    const float* n2w  = (const float*)d_in[3];
    const float* w1w  = (const float*)d_in[4];
    const float* w1b  = (const float*)d_in[5];
    const float* w2w  = (const float*)d_in[6];
    const float* w2b  = (const float*)d_in[7];
    const float* w3w  = (const float*)d_in[8];
    const float* w3b  = (const float*)d_in[9];
    float* y = (float*)d_out;

    k_prep<<<NBALL + 128, 256>>>(x, pos, n1w, w1w, w2w, w3w);
    k_route<<<512, 128>>>();
    k_attn<<<NPTS, 256>>>(x);
    k_mlp<<<NPTS / 16, 256>>>(n2w, w1b, w2b, w3b, y);
}

// round 15
// speedup vs baseline: 1.0642x; 1.0642x over previous
#include <cuda_runtime.h>
#include <math.h>
#include <stdint.h>

#define NPTS 8192
#define MB   64
#define NBALL 128
#define DIM  64
#define NH   8
#define EHD  8
#define HID  256
#define EPSF 1.1920929e-07f

// ---------------- scratch ----------------
__device__ float    g_xat[NH * NPTS * EHD];
__device__ float    g_keyst[NH * NBALL * EHD];
__device__ int      g_idx[NH * NPTS * 2];
__device__ float    g_h[NPTS * DIM];       // residual stream
// packed tf32 B-fragments, 4 words/lane = [k8even r0, k8even r1, k8odd r0, k8odd r1]
__device__ uint32_t g_w1p[16384];   // [n8:32][k8p:4][lane:32][word:4]
__device__ uint32_t g_w2p[16384];
__device__ uint32_t g_w3p[16384];   // [n8:8][k8p:16][lane:32][word:4]

__device__ __forceinline__ uint32_t f2tf32(float f) {
    uint32_t u;
    asm("cvt.rna.tf32.f32 %0, %1;" : "=r"(u) : "f"(f));
    return u;
}
__device__ __forceinline__ void mma_tf32(float* c, const uint32_t* a,
                                         uint32_t b0, uint32_t b1) {
    asm volatile(
        "mma.sync.aligned.m16n8k8.row.col.f32.tf32.tf32.f32 "
        "{%0,%1,%2,%3}, {%4,%5,%6,%7}, {%8,%9}, {%0,%1,%2,%3};"
        : "+f"(c[0]), "+f"(c[1]), "+f"(c[2]), "+f"(c[3])
        : "r"(a[0]), "r"(a[1]), "r"(a[2]), "r"(a[3]), "r"(b0), "r"(b1));
}

// ---------------- K1: ball prep (tree reductions) + weight frag build -------
__global__ void k_prep(const float* __restrict__ x,
                       const float* __restrict__ pos,
                       const float* __restrict__ n1w,
                       const float* __restrict__ w1,
                       const float* __restrict__ w2,
                       const float* __restrict__ w3) {
    int blk = blockIdx.x, tid = threadIdx.x;
    if (blk >= NBALL) {
        int grp = blk - NBALL;
        int i = (grp & 63) * 256 + tid;       // 0..16383
        int word = i & 3, lane = (i >> 2) & 31;
        int j = word >> 1, r = word & 1;
        if (grp < 64) {
            int k8p = (i >> 7) & 3, n8 = i >> 9;
            int k8 = k8p * 2 + j;
            int k = k8 * 8 + (lane & 3) + r * 4;
            int n = n8 * 8 + (lane >> 2);
            g_w1p[i] = f2tf32(w1[n * DIM + k]);
            g_w2p[i] = f2tf32(w2[n * DIM + k]);
        } else {
            int k8p = (i >> 7) & 15, n8 = i >> 11;
            int k8 = k8p * 2 + j;
            int k = k8 * 8 + (lane & 3) + r * 4;
            int n = n8 * 8 + (lane >> 2);
            g_w3p[i] = f2tf32(w3[n * HID + k]);
        }
        return;
    }
    __shared__ float ps[MB][DIM + 1];
    __shared__ float pp[4][DIM];
    __shared__ float pm[DIM];
    __shared__ float wsm[DIM];
    const float* xb = x + blk * (MB * DIM);
    const float* pb = pos + blk * (MB * DIM);
    for (int i = tid; i < MB * DIM; i += 256) ps[i >> 6][i & 63] = pb[i];
    if (tid < DIM) wsm[tid] = n1w[tid];
    int r = tid >> 2, part = tid & 3, d0 = part * 16;
    float xv[16];
    {
        const float4* xr4 = (const float4*)(xb + r * DIM + d0);
        float4 a0 = xr4[0], a1 = xr4[1], a2 = xr4[2], a3 = xr4[3];
        xv[0] = a0.x; xv[1] = a0.y; xv[2] = a0.z; xv[3] = a0.w;
        xv[4] = a1.x; xv[5] = a1.y; xv[6] = a1.z; xv[7] = a1.w;
        xv[8] = a2.x; xv[9] = a2.y; xv[10] = a2.z; xv[11] = a2.w;
        xv[12] = a3.x; xv[13] = a3.y; xv[14] = a3.z; xv[15] = a3.w;
    }
    float ss = 0.f;
    #pragma unroll
    for (int j = 0; j < 16; j++) ss += xv[j] * xv[j];
    ss += __shfl_xor_sync(0xffffffffu, ss, 1);
    ss += __shfl_xor_sync(0xffffffffu, ss, 2);
    float rs = rsqrtf(ss * (1.f / DIM) + EPSF);
    __syncthreads();
    {
        int d = tid & 63, c = tid >> 6;
        float s = 0.f;
        #pragma unroll
        for (int rr = 0; rr < 16; rr++) s += ps[c * 16 + rr][d];
        pp[c][d] = s;
    }
    __syncthreads();
    if (tid < DIM)
        pm[tid] = (pp[0][tid] + pp[1][tid] + pp[2][tid] + pp[3][tid]) * (1.f / MB);
    __syncthreads();
    float vals[16];
    #pragma unroll
    for (int j = 0; j < 16; j++) {
        int d = d0 + j;
        vals[j] = xv[j] * rs * wsm[d] + ps[r][d] - pm[d];
        ps[r][d] = vals[j];
    }
    {
        int n = blk * MB + r;
        float* o0 = g_xat + (part * 2) * (NPTS * EHD) + n * EHD;
        float* o1 = o0 + NPTS * EHD;
        ((float4*)o0)[0] = make_float4(vals[0], vals[1], vals[2], vals[3]);
        ((float4*)o0)[1] = make_float4(vals[4], vals[5], vals[6], vals[7]);
        ((float4*)o1)[0] = make_float4(vals[8], vals[9], vals[10], vals[11]);
        ((float4*)o1)[1] = make_float4(vals[12], vals[13], vals[14], vals[15]);
    }
    __syncthreads();
    {
        int d = tid & 63, c = tid >> 6;
        float s = 0.f;
        #pragma unroll
        for (int rr = 0; rr < 16; rr++) s += ps[c * 16 + rr][d];
        pp[c][d] = s;
    }
    __syncthreads();
    if (tid < DIM) {
        float s = (pp[0][tid] + pp[1][tid] + pp[2][tid] + pp[3][tid]) * (1.f / MB);
        g_keyst[(tid >> 3) * (NBALL * EHD) + blk * EHD + (tid & 7)] = s;
    }
}

// ---------------- K2: routing (smem-cached keys, 512 blocks x 128 thr) ------
__global__ void k_route() {
    __shared__ float4 ks[NBALL * 2];
    int h = blockIdx.x >> 6;
    int n = (blockIdx.x & 63) * 128 + threadIdx.x;
    const float4* kg = (const float4*)(g_keyst + h * (NBALL * EHD));
    ks[threadIdx.x] = kg[threadIdx.x];
    ks[threadIdx.x + 128] = kg[threadIdx.x + 128];
    __syncthreads();
    const float4* qp = (const float4*)(g_xat + h * (NPTS * EHD) + n * EHD);
    float4 qa = qp[0], qb = qp[1];
    float v0 = -3.4e38f, v1 = -3.4e38f;
    int i0 = 0, i1 = 0;
    #pragma unroll 4
    for (int b = 0; b < NBALL; b++) {
        float4 kA = ks[b * 2], kB = ks[b * 2 + 1];
        float s = qa.x * kA.x + qa.y * kA.y + qa.z * kA.z + qa.w * kA.w
                + qb.x * kB.x + qb.y * kB.y + qb.z * kB.z + qb.w * kB.w;
        if (s > v0) { v1 = v0; i1 = i0; v0 = s; i0 = b; }
        else if (s > v1) { v1 = s; i1 = b; }
    }
    int o = (h * NPTS + n) * 2;
    g_idx[o] = i0;
    g_idx[o + 1] = i1;
}

// ---------------- K3: attention, one block per QUERY BALL (L1 reuse) --------
// grid 128, 1024 threads (32 warps). Warp w: fixed head h=w&7, 16 points
// p = (w>>3) + 4i of this ball. Picks of co-ball points cluster -> kv rows
// stay L1-resident for the block's lifetime.
__global__ void __launch_bounds__(1024, 1) k_attn(const float* __restrict__ x) {
    int ball = blockIdx.x;
    int warp = threadIdx.x >> 5, lane = threadIdx.x & 31;
    int h = warp & 7;
    int pbase = warp >> 3;                 // 0..3
    const float* hb = g_xat + h * (NPTS * EHD);
    const float scale = 0.35355339059327373f;  // 1/sqrt(8)

    for (int i = 0; i < 16; i++) {
        int p = pbase + (i << 2);          // 0..63
        int n = ball * MB + p;
        const float4* qp = (const float4*)(hb + n * EHD);
        float4 qa = qp[0], qb = qp[1];
        float4 qh = (lane & 1) ? qb : qa;
        int base = (h * NPTS + n) * 2;
        int b0 = g_idx[base], b1 = g_idx[base + 1];
        const float4* p0 = (const float4*)(hb + b0 * (MB * EHD));
        const float4* p1 = (const float4*)(hb + b1 * (MB * EHD));

        float4 v[8];
        #pragma unroll
        for (int c = 0; c < 4; c++) v[c] = p0[c * 32 + lane];
        #pragma unroll
        for (int c = 0; c < 4; c++) v[4 + c] = p1[c * 32 + lane];

        float s[8];
        #pragma unroll
        for (int k = 0; k < 8; k++) {
            float part = qh.x * v[k].x + qh.y * v[k].y + qh.z * v[k].z + qh.w * v[k].w;
            s[k] = (part + __shfl_xor_sync(0xffffffffu, part, 1)) * scale;
        }
        float m = s[0];
        #pragma unroll
        for (int k = 1; k < 8; k++) m = fmaxf(m, s[k]);
        #pragma unroll
        for (int o = 16; o >= 1; o >>= 1) m = fmaxf(m, __shfl_xor_sync(0xffffffffu, m, o));
        float pr[8], lsum = 0.f;
        #pragma unroll
        for (int k = 0; k < 8; k++) { pr[k] = __expf(s[k] - m); lsum += pr[k]; }
        #pragma unroll
        for (int o = 16; o >= 1; o >>= 1) lsum += __shfl_xor_sync(0xffffffffu, lsum, o);
        float inv = 2.f / lsum;            // each row counted twice warp-wide

        float4 acc = make_float4(0.f, 0.f, 0.f, 0.f);
        #pragma unroll
        for (int k = 0; k < 8; k++) {
            acc.x += pr[k] * v[k].x; acc.y += pr[k] * v[k].y;
            acc.z += pr[k] * v[k].z; acc.w += pr[k] * v[k].w;
        }
        #pragma unroll
        for (int o = 2; o <= 16; o <<= 1) {
            acc.x += __shfl_xor_sync(0xffffffffu, acc.x, o);
            acc.y += __shfl_xor_sync(0xffffffffu, acc.y, o);
            acc.z += __shfl_xor_sync(0xffffffffu, acc.z, o);
            acc.w += __shfl_xor_sync(0xffffffffu, acc.w, o);
        }
        if (lane < 2) {
            int off = n * DIM + h * EHD + lane * 4;
            float4 xr = *(const float4*)(x + off);
            float4 o;
            o.x = xr.x + acc.x * inv;
            o.y = xr.y + acc.y * inv;
            o.z = xr.z + acc.z * inv;
            o.w = xr.w + acc.w * inv;
            *(float4*)(g_h + off) = o;
        }
    }
}

// ---------------- K4: fully fused MLP (R12 proven version) ----------------
__global__ void __launch_bounds__(256, 2)
k_mlp(const float* __restrict__ n2w,
      const float* __restrict__ b1p,
      const float* __restrict__ b2p,
      const float* __restrict__ b3p,
      float* __restrict__ y) {
    __shared__ uint32_t safr[2 * 8 * 32 * 4];    // 8KB  input A-frags
    __shared__ uint32_t hfr[2 * 32 * 32 * 4];    // 32KB hidden A-frags
    __shared__ float sb1[HID], sb2[HID];
    int tid = threadIdx.x;
    int r0 = blockIdx.x * 32;
    sb1[tid] = b1p[tid];
    sb2[tid] = b2p[tid];
    // ---- rmsnorm ----
    {
        int rr = tid >> 3, p = tid & 7;
        const float* hr = g_h + (r0 + rr) * DIM + p * 8;
        float hv[8], ss = 0.f;
        #pragma unroll
        for (int j = 0; j < 8; j++) { hv[j] = hr[j]; ss += hv[j] * hv[j]; }
        ss += __shfl_xor_sync(0xffffffffu, ss, 1);
        ss += __shfl_xor_sync(0xffffffffu, ss, 2);
        ss += __shfl_xor_sync(0xffffffffu, ss, 4);
        float rs = rsqrtf(ss * (1.f / DIM) + EPSF);
        int m16 = rr >> 4;
        #pragma unroll
        for (int j = 0; j < 8; j++) {
            int k = p * 8 + j;
            float tv = hv[j] * rs * n2w[k];
            int lane_t = ((rr & 7) << 2) | (j & 3);
            int reg = ((rr >> 3) & 1) | ((j >> 2) << 1);
            safr[(((m16 * 8 + p) * 32 + lane_t) << 2) + reg] = f2tf32(tv);
        }
    }
    __syncthreads();
    int warp = tid >> 5, lane = tid & 31;
    // ---- phase 1: dual GEMM, warp w -> n8 {4w..4w+3} ----
    {
        float c1[2][4][4], c2[2][4][4];
        #pragma unroll
        for (int m = 0; m < 2; m++)
            #pragma unroll
            for (int n = 0; n < 4; n++)
                #pragma unroll
                for (int j = 0; j < 4; j++) { c1[m][n][j] = 0.f; c2[m][n][j] = 0.f; }
        #pragma unroll
        for (int k8p = 0; k8p < 4; k8p++) {
            uint4 b1v[4], b2v[4];
            #pragma unroll
            for (int ns = 0; ns < 4; ns++) {
                int n8 = warp * 4 + ns;
                int bi = (((n8 * 4 + k8p) * 32 + lane) << 2);
                b1v[ns] = *(const uint4*)(g_w1p + bi);
                b2v[ns] = *(const uint4*)(g_w2p + bi);
            }
            #pragma unroll
            for (int j = 0; j < 2; j++) {
                int k8 = k8p * 2 + j;
                uint32_t a[2][4];
                #pragma unroll
                for (int m = 0; m < 2; m++) {
                    uint4 av = *(const uint4*)(safr + (((m * 8 + k8) * 32 + lane) << 2));
                    a[m][0] = av.x; a[m][1] = av.y; a[m][2] = av.z; a[m][3] = av.w;
                }
                #pragma unroll
                for (int ns = 0; ns < 4; ns++) {
                    uint32_t w10 = j ? b1v[ns].z : b1v[ns].x;
                    uint32_t w11 = j ? b1v[ns].w : b1v[ns].y;
                    uint32_t w20 = j ? b2v[ns].z : b2v[ns].x;
                    uint32_t w21 = j ? b2v[ns].w : b2v[ns].y;
                    #pragma unroll
                    for (int m = 0; m < 2; m++) {
                        mma_tf32(c1[m][ns], a[m], w10, w11);
                        mma_tf32(c2[m][ns], a[m], w20, w21);
                    }
                }
            }
        }
        // SwiGLU epilogue -> smem hidden A-fragments
        int ka = 2 * (lane & 3);
        int lta = ((lane >> 2) << 2) | (ka & 3);
        int ltb = ((lane >> 2) << 2) | ((ka + 1) & 3);
        int khi = (ka >> 2) << 1;
        #pragma unroll
        for (int m = 0; m < 2; m++) {
            #pragma unroll
            for (int ns = 0; ns < 4; ns++) {
                int k8h = warp * 4 + ns;
                int colb = k8h * 8 + ka;
                float bb1a = sb1[colb], bb1b = sb1[colb + 1];
                float bb2a = sb2[colb], bb2b = sb2[colb + 1];
                uint32_t* basep = hfr + (((m * 32 + k8h) * 32) << 2);
                #pragma unroll
                for (int half = 0; half < 2; half++) {
                    float u1a = c1[m][ns][half * 2] + bb1a;
                    float u1b = c1[m][ns][half * 2 + 1] + bb1b;
                    float ha = (c2[m][ns][half * 2] + bb2a) * u1a * (1.f / (1.f + __expf(-u1a)));
                    float hb = (c2[m][ns][half * 2 + 1] + bb2b) * u1b * (1.f / (1.f + __expf(-u1b)));
                    basep[(lta << 2) + (half | khi)] = f2tf32(ha);
                    basep[(ltb << 2) + (half | khi)] = f2tf32(hb);
                }
            }
        }
    }
    __syncthreads();
    // ---- phase 2: down-proj, warp w -> output n8 = w ----
    {
        float c[2][4];
        #pragma unroll
        for (int m = 0; m < 2; m++)
            #pragma unroll
            for (int j = 0; j < 4; j++) c[m][j] = 0.f;
        #pragma unroll 4
        for (int k8p = 0; k8p < 16; k8p++) {
            uint4 bv = *(const uint4*)(g_w3p + (((warp * 16 + k8p) * 32 + lane) << 2));
            #pragma unroll
            for (int j = 0; j < 2; j++) {
                int k8 = k8p * 2 + j;
                uint32_t w0 = j ? bv.z : bv.x;
                uint32_t w1 = j ? bv.w : bv.y;
                #pragma unroll
                for (int m = 0; m < 2; m++) {
                    uint4 av = *(const uint4*)(hfr + (((m * 32 + k8) * 32 + lane) << 2));
                    uint32_t a[4] = {av.x, av.y, av.z, av.w};
                    mma_tf32(c[m], a, w0, w1);
                }
            }
        }
        int colb = warp * 8 + 2 * (lane & 3);
        float bva = b3p[colb], bvb = b3p[colb + 1];
        #pragma unroll
        for (int m = 0; m < 2; m++) {
            #pragma unroll
            for (int half = 0; half < 2; half++) {
                int row = r0 + m * 16 + (lane >> 2) + half * 8;
                float2 hres = *(const float2*)(g_h + row * DIM + colb);
                float2 o;
                o.x = hres.x + c[m][half * 2] + bva;
                o.y = hres.y + c[m][half * 2 + 1] + bvb;
                *(float2*)(y + row * DIM + colb) = o;
            }
        }
    }
}

// ---------------- launch ----------------
extern "C" void kernel_launch(void* const* d_in, const int* in_sizes, int n_in,
                              void* d_out, int out_size) {
    const float* x    = (const float*)d_in[0];
    const float* pos  = (const float*)d_in[1];
    const float* n1w  = (const float*)d_in[2];
    const float* n2w  = (const float*)d_in[3];
    const float* w1w  = (const float*)d_in[4];
    const float* w1b  = (const float*)d_in[5];
    const float* w2w  = (const float*)d_in[6];
    const float* w2b  = (const float*)d_in[7];
    const float* w3w  = (const float*)d_in[8];
    const float* w3b  = (const float*)d_in[9];
    float* y = (float*)d_out;

    k_prep<<<NBALL + 128, 256>>>(x, pos, n1w, w1w, w2w, w3w);
    k_route<<<512, 128>>>();
    k_attn<<<NBALL, 1024>>>(x);
    k_mlp<<<NPTS / 32, 256>>>(n2w, w1b, w2b, w3b, y);
}

// round 16
// speedup vs baseline: 1.1452x; 1.0762x over previous
#include <cuda_runtime.h>
#include <cuda_fp16.h>
#include <math.h>
#include <stdint.h>

#define NPTS 8192
#define MB   64
#define NBALL 128
#define DIM  64
#define NH   8
#define EHD  8
#define HID  256
#define EPSF 1.1920929e-07f

// ---------------- scratch ----------------
__device__ float    g_xat[NH * NPTS * EHD];   // fp32 head-major (q + keys source)
__device__ __half   g_xah[NH * NPTS * EHD];   // fp16 head-major kv mirror
__device__ float    g_keyst[NH * NBALL * EHD];
__device__ int      g_idx[NH * NPTS * 2];
__device__ float    g_h[NPTS * DIM];          // residual stream
// packed tf32 B-fragments, 4 words/lane = [k8even r0, k8even r1, k8odd r0, k8odd r1]
__device__ uint32_t g_w1p[16384];   // [n8:32][k8p:4][lane:32][word:4]
__device__ uint32_t g_w2p[16384];
__device__ uint32_t g_w3p[16384];   // [n8:8][k8p:16][lane:32][word:4]

__device__ __forceinline__ uint32_t f2tf32(float f) {
    uint32_t u;
    asm("cvt.rna.tf32.f32 %0, %1;" : "=r"(u) : "f"(f));
    return u;
}
__device__ __forceinline__ void mma_tf32(float* c, const uint32_t* a,
                                         uint32_t b0, uint32_t b1) {
    asm volatile(
        "mma.sync.aligned.m16n8k8.row.col.f32.tf32.tf32.f32 "
        "{%0,%1,%2,%3}, {%4,%5,%6,%7}, {%8,%9}, {%0,%1,%2,%3};"
        : "+f"(c[0]), "+f"(c[1]), "+f"(c[2]), "+f"(c[3])
        : "r"(a[0]), "r"(a[1]), "r"(a[2]), "r"(a[3]), "r"(b0), "r"(b1));
}

// ---------------- K1: ball prep (tree reductions) + weight frag build -------
__global__ void k_prep(const float* __restrict__ x,
                       const float* __restrict__ pos,
                       const float* __restrict__ n1w,
                       const float* __restrict__ w1,
                       const float* __restrict__ w2,
                       const float* __restrict__ w3) {
    int blk = blockIdx.x, tid = threadIdx.x;
    if (blk >= NBALL) {
        int grp = blk - NBALL;
        int i = (grp & 63) * 256 + tid;       // 0..16383
        int word = i & 3, lane = (i >> 2) & 31;
        int j = word >> 1, r = word & 1;
        if (grp < 64) {
            int k8p = (i >> 7) & 3, n8 = i >> 9;
            int k8 = k8p * 2 + j;
            int k = k8 * 8 + (lane & 3) + r * 4;
            int n = n8 * 8 + (lane >> 2);
            g_w1p[i] = f2tf32(w1[n * DIM + k]);
            g_w2p[i] = f2tf32(w2[n * DIM + k]);
        } else {
            int k8p = (i >> 7) & 15, n8 = i >> 11;
            int k8 = k8p * 2 + j;
            int k = k8 * 8 + (lane & 3) + r * 4;
            int n = n8 * 8 + (lane >> 2);
            g_w3p[i] = f2tf32(w3[n * HID + k]);
        }
        return;
    }
    __shared__ float ps[MB][DIM + 1];
    __shared__ float pp[4][DIM];
    __shared__ float pm[DIM];
    __shared__ float wsm[DIM];
    const float* xb = x + blk * (MB * DIM);
    const float* pb = pos + blk * (MB * DIM);
    for (int i = tid; i < MB * DIM; i += 256) ps[i >> 6][i & 63] = pb[i];
    if (tid < DIM) wsm[tid] = n1w[tid];
    int r = tid >> 2, part = tid & 3, d0 = part * 16;
    float xv[16];
    {
        const float4* xr4 = (const float4*)(xb + r * DIM + d0);
        float4 a0 = xr4[0], a1 = xr4[1], a2 = xr4[2], a3 = xr4[3];
        xv[0] = a0.x; xv[1] = a0.y; xv[2] = a0.z; xv[3] = a0.w;
        xv[4] = a1.x; xv[5] = a1.y; xv[6] = a1.z; xv[7] = a1.w;
        xv[8] = a2.x; xv[9] = a2.y; xv[10] = a2.z; xv[11] = a2.w;
        xv[12] = a3.x; xv[13] = a3.y; xv[14] = a3.z; xv[15] = a3.w;
    }
    float ss = 0.f;
    #pragma unroll
    for (int j = 0; j < 16; j++) ss += xv[j] * xv[j];
    ss += __shfl_xor_sync(0xffffffffu, ss, 1);
    ss += __shfl_xor_sync(0xffffffffu, ss, 2);
    float rs = rsqrtf(ss * (1.f / DIM) + EPSF);
    __syncthreads();
    {
        int d = tid & 63, c = tid >> 6;
        float s = 0.f;
        #pragma unroll
        for (int rr = 0; rr < 16; rr++) s += ps[c * 16 + rr][d];
        pp[c][d] = s;
    }
    __syncthreads();
    if (tid < DIM)
        pm[tid] = (pp[0][tid] + pp[1][tid] + pp[2][tid] + pp[3][tid]) * (1.f / MB);
    __syncthreads();
    float vals[16];
    #pragma unroll
    for (int j = 0; j < 16; j++) {
        int d = d0 + j;
        vals[j] = xv[j] * rs * wsm[d] + ps[r][d] - pm[d];
        ps[r][d] = vals[j];
    }
    {
        int n = blk * MB + r;
        float* o0 = g_xat + (part * 2) * (NPTS * EHD) + n * EHD;
        float* o1 = o0 + NPTS * EHD;
        ((float4*)o0)[0] = make_float4(vals[0], vals[1], vals[2], vals[3]);
        ((float4*)o0)[1] = make_float4(vals[4], vals[5], vals[6], vals[7]);
        ((float4*)o1)[0] = make_float4(vals[8], vals[9], vals[10], vals[11]);
        ((float4*)o1)[1] = make_float4(vals[12], vals[13], vals[14], vals[15]);
        // fp16 kv mirror: one uint4 (8 halves) per head-row
        uint4 u0, u1;
        ((__half2*)&u0)[0] = __floats2half2_rn(vals[0], vals[1]);
        ((__half2*)&u0)[1] = __floats2half2_rn(vals[2], vals[3]);
        ((__half2*)&u0)[2] = __floats2half2_rn(vals[4], vals[5]);
        ((__half2*)&u0)[3] = __floats2half2_rn(vals[6], vals[7]);
        ((__half2*)&u1)[0] = __floats2half2_rn(vals[8], vals[9]);
        ((__half2*)&u1)[1] = __floats2half2_rn(vals[10], vals[11]);
        ((__half2*)&u1)[2] = __floats2half2_rn(vals[12], vals[13]);
        ((__half2*)&u1)[3] = __floats2half2_rn(vals[14], vals[15]);
        ((uint4*)(g_xah + (part * 2) * (NPTS * EHD)))[n] = u0;
        ((uint4*)(g_xah + (part * 2 + 1) * (NPTS * EHD)))[n] = u1;
    }
    __syncthreads();
    {
        int d = tid & 63, c = tid >> 6;
        float s = 0.f;
        #pragma unroll
        for (int rr = 0; rr < 16; rr++) s += ps[c * 16 + rr][d];
        pp[c][d] = s;
    }
    __syncthreads();
    if (tid < DIM) {
        float s = (pp[0][tid] + pp[1][tid] + pp[2][tid] + pp[3][tid]) * (1.f / MB);
        g_keyst[(tid >> 3) * (NBALL * EHD) + blk * EHD + (tid & 7)] = s;
    }
}

// ---------------- K2: routing (smem-cached keys, 512 blocks x 128 thr) ------
__global__ void k_route() {
    __shared__ float4 ks[NBALL * 2];
    int h = blockIdx.x >> 6;
    int n = (blockIdx.x & 63) * 128 + threadIdx.x;
    const float4* kg = (const float4*)(g_keyst + h * (NBALL * EHD));
    ks[threadIdx.x] = kg[threadIdx.x];
    ks[threadIdx.x + 128] = kg[threadIdx.x + 128];
    __syncthreads();
    const float4* qp = (const float4*)(g_xat + h * (NPTS * EHD) + n * EHD);
    float4 qa = qp[0], qb = qp[1];
    float v0 = -3.4e38f, v1 = -3.4e38f;
    int i0 = 0, i1 = 0;
    #pragma unroll 4
    for (int b = 0; b < NBALL; b++) {
        float4 kA = ks[b * 2], kB = ks[b * 2 + 1];
        float s = qa.x * kA.x + qa.y * kA.y + qa.z * kA.z + qa.w * kA.w
                + qb.x * kB.x + qb.y * kB.y + qb.z * kB.z + qb.w * kB.w;
        if (s > v0) { v1 = v0; i1 = i0; v0 = s; i0 = b; }
        else if (s > v1) { v1 = s; i1 = b; }
    }
    int o = (h * NPTS + n) * 2;
    g_idx[o] = i0;
    g_idx[o + 1] = i1;
}

// ---------------- K3: attention (one warp per (n,h), fp16 kv) ---------------
// Each lane loads FULL 8-elem rows (uint4 of halves): 2 rows per ball.
__global__ void k_attn(const float* __restrict__ x) {
    int n = blockIdx.x;
    int h = threadIdx.x >> 5, lane = threadIdx.x & 31;
    const float* hb = g_xat + h * (NPTS * EHD);
    const float4* qp = (const float4*)(hb + n * EHD);
    float4 qa = qp[0], qb = qp[1];
    int base = (h * NPTS + n) * 2;
    int b0 = g_idx[base], b1 = g_idx[base + 1];
    const uint4* p0 = (const uint4*)(g_xah + (h * NPTS + b0 * MB) * EHD);
    const uint4* p1 = (const uint4*)(g_xah + (h * NPTS + b1 * MB) * EHD);
    const float scale = 0.35355339059327373f;  // 1/sqrt(8)

    // 4 full rows per lane: 2 from each ball
    float v[4][8];
    float s[4];
    #pragma unroll
    for (int r = 0; r < 4; r++) {
        uint4 u = (r < 2) ? p0[(r & 1) * 32 + lane] : p1[(r & 1) * 32 + lane];
        const __half2* hp = (const __half2*)&u;
        #pragma unroll
        for (int e = 0; e < 4; e++) {
            float2 f = __half22float2(hp[e]);
            v[r][e * 2] = f.x;
            v[r][e * 2 + 1] = f.y;
        }
        s[r] = (qa.x * v[r][0] + qa.y * v[r][1] + qa.z * v[r][2] + qa.w * v[r][3]
              + qb.x * v[r][4] + qb.y * v[r][5] + qb.z * v[r][6] + qb.w * v[r][7]) * scale;
    }
    float m = fmaxf(fmaxf(s[0], s[1]), fmaxf(s[2], s[3]));
    #pragma unroll
    for (int o = 16; o >= 1; o >>= 1) m = fmaxf(m, __shfl_xor_sync(0xffffffffu, m, o));
    float p[4], lsum = 0.f;
    #pragma unroll
    for (int r = 0; r < 4; r++) { p[r] = __expf(s[r] - m); lsum += p[r]; }
    #pragma unroll
    for (int o = 16; o >= 1; o >>= 1) lsum += __shfl_xor_sync(0xffffffffu, lsum, o);
    float inv = 1.f / lsum;   // each row counted exactly once

    float acc[8];
    #pragma unroll
    for (int e = 0; e < 8; e++) acc[e] = 0.f;
    #pragma unroll
    for (int r = 0; r < 4; r++)
        #pragma unroll
        for (int e = 0; e < 8; e++) acc[e] += p[r] * v[r][e];
    #pragma unroll
    for (int o = 1; o <= 16; o <<= 1)
        #pragma unroll
        for (int e = 0; e < 8; e++)
            acc[e] += __shfl_xor_sync(0xffffffffu, acc[e], o);
    if (lane < 2) {
        int off = n * DIM + h * EHD + lane * 4;
        float4 xr = *(const float4*)(x + off);
        float4 o;
        o.x = xr.x + acc[lane * 4 + 0] * inv;
        o.y = xr.y + acc[lane * 4 + 1] * inv;
        o.z = xr.z + acc[lane * 4 + 2] * inv;
        o.w = xr.w + acc[lane * 4 + 3] * inv;
        *(float4*)(g_h + off) = o;
    }
}

// ---------------- K4: fully fused MLP (R12 proven version) ----------------
__global__ void __launch_bounds__(256, 2)
k_mlp(const float* __restrict__ n2w,
      const float* __restrict__ b1p,
      const float* __restrict__ b2p,
      const float* __restrict__ b3p,
      float* __restrict__ y) {
    __shared__ uint32_t safr[2 * 8 * 32 * 4];    // 8KB  input A-frags
    __shared__ uint32_t hfr[2 * 32 * 32 * 4];    // 32KB hidden A-frags
    __shared__ float sb1[HID], sb2[HID];
    int tid = threadIdx.x;
    int r0 = blockIdx.x * 32;
    sb1[tid] = b1p[tid];
    sb2[tid] = b2p[tid];
    // ---- rmsnorm ----
    {
        int rr = tid >> 3, p = tid & 7;
        const float* hr = g_h + (r0 + rr) * DIM + p * 8;
        float hv[8], ss = 0.f;
        #pragma unroll
        for (int j = 0; j < 8; j++) { hv[j] = hr[j]; ss += hv[j] * hv[j]; }
        ss += __shfl_xor_sync(0xffffffffu, ss, 1);
        ss += __shfl_xor_sync(0xffffffffu, ss, 2);
        ss += __shfl_xor_sync(0xffffffffu, ss, 4);
        float rs = rsqrtf(ss * (1.f / DIM) + EPSF);
        int m16 = rr >> 4;
        #pragma unroll
        for (int j = 0; j < 8; j++) {
            int k = p * 8 + j;
            float tv = hv[j] * rs * n2w[k];
            int lane_t = ((rr & 7) << 2) | (j & 3);
            int reg = ((rr >> 3) & 1) | ((j >> 2) << 1);
            safr[(((m16 * 8 + p) * 32 + lane_t) << 2) + reg] = f2tf32(tv);
        }
    }
    __syncthreads();
    int warp = tid >> 5, lane = tid & 31;
    // ---- phase 1: dual GEMM, warp w -> n8 {4w..4w+3} ----
    {
        float c1[2][4][4], c2[2][4][4];
        #pragma unroll
        for (int m = 0; m < 2; m++)
            #pragma unroll
            for (int n = 0; n < 4; n++)
                #pragma unroll
                for (int j = 0; j < 4; j++) { c1[m][n][j] = 0.f; c2[m][n][j] = 0.f; }
        #pragma unroll
        for (int k8p = 0; k8p < 4; k8p++) {
            uint4 b1v[4], b2v[4];
            #pragma unroll
            for (int ns = 0; ns < 4; ns++) {
                int n8 = warp * 4 + ns;
                int bi = (((n8 * 4 + k8p) * 32 + lane) << 2);
                b1v[ns] = *(const uint4*)(g_w1p + bi);
                b2v[ns] = *(const uint4*)(g_w2p + bi);
            }
            #pragma unroll
            for (int j = 0; j < 2; j++) {
                int k8 = k8p * 2 + j;
                uint32_t a[2][4];
                #pragma unroll
                for (int m = 0; m < 2; m++) {
                    uint4 av = *(const uint4*)(safr + (((m * 8 + k8) * 32 + lane) << 2));
                    a[m][0] = av.x; a[m][1] = av.y; a[m][2] = av.z; a[m][3] = av.w;
                }
                #pragma unroll
                for (int ns = 0; ns < 4; ns++) {
                    uint32_t w10 = j ? b1v[ns].z : b1v[ns].x;
                    uint32_t w11 = j ? b1v[ns].w : b1v[ns].y;
                    uint32_t w20 = j ? b2v[ns].z : b2v[ns].x;
                    uint32_t w21 = j ? b2v[ns].w : b2v[ns].y;
                    #pragma unroll
                    for (int m = 0; m < 2; m++) {
                        mma_tf32(c1[m][ns], a[m], w10, w11);
                        mma_tf32(c2[m][ns], a[m], w20, w21);
                    }
                }
            }
        }
        // SwiGLU epilogue -> smem hidden A-fragments
        int ka = 2 * (lane & 3);
        int lta = ((lane >> 2) << 2) | (ka & 3);
        int ltb = ((lane >> 2) << 2) | ((ka + 1) & 3);
        int khi = (ka >> 2) << 1;
        #pragma unroll
        for (int m = 0; m < 2; m++) {
            #pragma unroll
            for (int ns = 0; ns < 4; ns++) {
                int k8h = warp * 4 + ns;
                int colb = k8h * 8 + ka;
                float bb1a = sb1[colb], bb1b = sb1[colb + 1];
                float bb2a = sb2[colb], bb2b = sb2[colb + 1];
                uint32_t* basep = hfr + (((m * 32 + k8h) * 32) << 2);
                #pragma unroll
                for (int half = 0; half < 2; half++) {
                    float u1a = c1[m][ns][half * 2] + bb1a;
                    float u1b = c1[m][ns][half * 2 + 1] + bb1b;
                    float ha = (c2[m][ns][half * 2] + bb2a) * u1a * (1.f / (1.f + __expf(-u1a)));
                    float hb = (c2[m][ns][half * 2 + 1] + bb2b) * u1b * (1.f / (1.f + __expf(-u1b)));
                    basep[(lta << 2) + (half | khi)] = f2tf32(ha);
                    basep[(ltb << 2) + (half | khi)] = f2tf32(hb);
                }
            }
        }
    }
    __syncthreads();
    // ---- phase 2: down-proj, warp w -> output n8 = w ----
    {
        float c[2][4];
        #pragma unroll
        for (int m = 0; m < 2; m++)
            #pragma unroll
            for (int j = 0; j < 4; j++) c[m][j] = 0.f;
        #pragma unroll 4
        for (int k8p = 0; k8p < 16; k8p++) {
            uint4 bv = *(const uint4*)(g_w3p + (((warp * 16 + k8p) * 32 + lane) << 2));
            #pragma unroll
            for (int j = 0; j < 2; j++) {
                int k8 = k8p * 2 + j;
                uint32_t w0 = j ? bv.z : bv.x;
                uint32_t w1 = j ? bv.w : bv.y;
                #pragma unroll
                for (int m = 0; m < 2; m++) {
                    uint4 av = *(const uint4*)(hfr + (((m * 32 + k8) * 32 + lane) << 2));
                    uint32_t a[4] = {av.x, av.y, av.z, av.w};
                    mma_tf32(c[m], a, w0, w1);
                }
            }
        }
        int colb = warp * 8 + 2 * (lane & 3);
        float bva = b3p[colb], bvb = b3p[colb + 1];
        #pragma unroll
        for (int m = 0; m < 2; m++) {
            #pragma unroll
            for (int half = 0; half < 2; half++) {
                int row = r0 + m * 16 + (lane >> 2) + half * 8;
                float2 hres = *(const float2*)(g_h + row * DIM + colb);
                float2 o;
                o.x = hres.x + c[m][half * 2] + bva;
                o.y = hres.y + c[m][half * 2 + 1] + bvb;
                *(float2*)(y + row * DIM + colb) = o;
            }
        }
    }
}

// ---------------- launch ----------------
extern "C" void kernel_launch(void* const* d_in, const int* in_sizes, int n_in,
                              void* d_out, int out_size) {
    const float* x    = (const float*)d_in[0];
    const float* pos  = (const float*)d_in[1];
    const float* n1w  = (const float*)d_in[2];
    const float* n2w  = (const float*)d_in[3];
    const float* w1w  = (const float*)d_in[4];
    const float* w1b  = (const float*)d_in[5];
    const float* w2w  = (const float*)d_in[6];
    const float* w2b  = (const float*)d_in[7];
    const float* w3w  = (const float*)d_in[8];
    const float* w3b  = (const float*)d_in[9];
    float* y = (float*)d_out;

    k_prep<<<NBALL + 128, 256>>>(x, pos, n1w, w1w, w2w, w3w);
    k_route<<<512, 128>>>();
    k_attn<<<NPTS, 256>>>(x);
    k_mlp<<<NPTS / 32, 256>>>(n2w, w1b, w2b, w3b, y);
}